// round 8
// baseline (speedup 1.0000x reference)
#include <cuda_runtime.h>
#include <cuda_fp16.h>
#include <math.h>

#define BATCH 4
#define CH    128
#define NTOK  4096
#define TQ    64
#define TK    64
#define QP    136   // Q/K/V smem pitch (halves); 272B stride -> conflict-free ldmatrix
#define PP    72    // P smem pitch (halves)
#define WPI   136   // qkv smem pitch

// fp16 staging buffers written by qkv kernel (Q pre-scaled by 1/sqrt(C)).
__device__ __half g_Q[BATCH * NTOK * CH];
__device__ __half g_K[BATCH * NTOK * CH];
__device__ __half g_V[BATCH * NTOK * CH];

// ---------------------------------------------------------------------------
// PTX helpers
// ---------------------------------------------------------------------------
__device__ __forceinline__ unsigned smem_u32(const void* p) {
    return (unsigned)__cvta_generic_to_shared(p);
}
__device__ __forceinline__ void cp16(unsigned dst, const void* src) {
    asm volatile("cp.async.cg.shared.global [%0], [%1], 16;\n" :: "r"(dst), "l"(src));
}
__device__ __forceinline__ void cp_commit() {
    asm volatile("cp.async.commit_group;\n");
}
template<int N> __device__ __forceinline__ void cp_wait() {
    asm volatile("cp.async.wait_group %0;\n" :: "n"(N));
}
__device__ __forceinline__ void ldsm4(unsigned addr, unsigned& a0, unsigned& a1,
                                      unsigned& a2, unsigned& a3) {
    asm volatile("ldmatrix.sync.aligned.m8n8.x4.shared.b16 {%0,%1,%2,%3}, [%4];\n"
                 : "=r"(a0), "=r"(a1), "=r"(a2), "=r"(a3) : "r"(addr));
}
__device__ __forceinline__ void ldsm4t(unsigned addr, unsigned& a0, unsigned& a1,
                                       unsigned& a2, unsigned& a3) {
    asm volatile("ldmatrix.sync.aligned.m8n8.x4.trans.shared.b16 {%0,%1,%2,%3}, [%4];\n"
                 : "=r"(a0), "=r"(a1), "=r"(a2), "=r"(a3) : "r"(addr));
}
__device__ __forceinline__ void mma16816(float& d0, float& d1, float& d2, float& d3,
                                         unsigned a0, unsigned a1, unsigned a2, unsigned a3,
                                         unsigned b0, unsigned b1) {
    asm volatile("mma.sync.aligned.m16n8k16.row.col.f32.f16.f16.f32 "
                 "{%0,%1,%2,%3}, {%4,%5,%6,%7}, {%8,%9}, {%0,%1,%2,%3};\n"
                 : "+f"(d0), "+f"(d1), "+f"(d2), "+f"(d3)
                 : "r"(a0), "r"(a1), "r"(a2), "r"(a3), "r"(b0), "r"(b1));
}

// ---------------------------------------------------------------------------
// Kernel 1: tensor-core QKV. Block = 128 tokens; computes Q,K,V projections.
// Warp = 16 tokens x 128 outputs. fp32 gmem -> fp16 smem -> mma (fp32 accum).
// ---------------------------------------------------------------------------
__global__ __launch_bounds__(256, 1)
void qkv_kernel(const float* __restrict__ prompt, const float* __restrict__ x,
                const float* __restrict__ Wq, const float* __restrict__ bq,
                const float* __restrict__ Wk, const float* __restrict__ bk,
                const float* __restrict__ Wv, const float* __restrict__ bv)
{
    extern __shared__ char smraw[];
    __half* Xp  = (__half*)smraw;           // prompt tile 128x136
    __half* Xx  = Xp  + 128 * WPI;          // x tile
    __half* Wqs = Xx  + 128 * WPI;          // 128x136 each
    __half* Wks = Wqs + 128 * WPI;
    __half* Wvs = Wks + 128 * WPI;
    float*  bqs = (float*)(Wvs + 128 * WPI);
    float*  bks = bqs + 128;
    float*  bvs = bks + 128;

    const int b  = blockIdx.x >> 5;
    const int nb = (blockIdx.x & 31) * 128;
    const int tid = threadIdx.x;

    for (int idx = tid; idx < 128 * 128; idx += 256) {
        int c = idx >> 7, t = idx & 127;
        size_t gofs = ((size_t)b * CH + c) * NTOK + nb + t;
        Xp[t * WPI + c] = __float2half(prompt[gofs]);
        Xx[t * WPI + c] = __float2half(x[gofs]);
    }
    for (int idx = tid; idx < 128 * 128; idx += 256) {
        int co = idx >> 7, c = idx & 127;
        Wqs[co * WPI + c] = __float2half(Wq[idx]);
        Wks[co * WPI + c] = __float2half(Wk[idx]);
        Wvs[co * WPI + c] = __float2half(Wv[idx]);
    }
    if (tid < 128) { bqs[tid] = bq[tid]; bks[tid] = bk[tid]; bvs[tid] = bv[tid]; }
    __syncthreads();

    const int lane = tid & 31, wid = tid >> 5;
    const int r0 = wid * 16;
    const int g = lane >> 2, qd = lane & 3;

    const unsigned aXp = smem_u32(Xp) + ((r0 + (lane & 15)) * WPI + (lane >> 4) * 8) * 2;
    const unsigned aXx = aXp + (unsigned)(128 * WPI * 2);
    const unsigned w4 = (((lane >> 4) * 8 + (lane & 7)) * WPI + ((lane >> 3) & 1) * 8) * 2;

    #pragma unroll 1
    for (int p = 0; p < 3; p++) {
        const unsigned aA = (p == 0) ? aXp : aXx;
        const unsigned aW = smem_u32(p == 0 ? Wqs : (p == 1 ? Wks : Wvs)) + w4;
        const float* bias = (p == 0) ? bqs : (p == 1) ? bks : bvs;
        __half* outg      = (p == 0) ? g_Q : (p == 1) ? g_K : g_V;
        const float os    = (p == 0) ? 0.0883883476483184f : 1.0f;

        float c[16][4];
        #pragma unroll
        for (int nt = 0; nt < 16; nt++) { c[nt][0] = c[nt][1] = c[nt][2] = c[nt][3] = 0.f; }

        #pragma unroll
        for (int ks = 0; ks < 8; ks++) {
            unsigned a0, a1, a2, a3;
            ldsm4(aA + ks * 32, a0, a1, a2, a3);
            #pragma unroll
            for (int ntp = 0; ntp < 8; ntp++) {
                unsigned b0, b1, b2, b3;
                ldsm4(aW + ntp * (16 * WPI * 2) + ks * 32, b0, b1, b2, b3);
                mma16816(c[2*ntp][0], c[2*ntp][1], c[2*ntp][2], c[2*ntp][3],
                         a0, a1, a2, a3, b0, b1);
                mma16816(c[2*ntp+1][0], c[2*ntp+1][1], c[2*ntp+1][2], c[2*ntp+1][3],
                         a0, a1, a2, a3, b2, b3);
            }
        }

        __half* row0 = outg + (size_t)(b * NTOK + nb + r0 + g) * CH;
        __half* row1 = row0 + 8 * CH;
        #pragma unroll
        for (int nt = 0; nt < 16; nt++) {
            int co = nt * 8 + 2 * qd;
            float b0v = bias[co], b1v = bias[co + 1];
            *(__half2*)(row0 + co) = __floats2half2_rn((c[nt][0] + b0v) * os, (c[nt][1] + b1v) * os);
            *(__half2*)(row1 + co) = __floats2half2_rn((c[nt][2] + b0v) * os, (c[nt][3] + b1v) * os);
        }
    }
}

// ---------------------------------------------------------------------------
// Kernel 2: fp16 tensor-core flash attention + residual + LayerNorm.
// Block = 64 queries, 4 warps, ~103KB smem -> 2 blocks/SM for latency overlap.
// Warp = 16 rows x 64 keys; warp-local softmax; x4 ldmatrix for K/V.
// ---------------------------------------------------------------------------
#define SMEM_Q   0                // 64*136*2 = 17408
#define SMEM_K   17408            // 2 bufs x 64*136*2 = 34816
#define SMEM_V   52224            // 34816
#define SMEM_P   87040            // 64*72*2 = 9216
#define SMEM_MK  96256            // 4096 halves = 8192
#define SMEM_GB  104448           // 256 floats = 1024
#define SMEM_TOT 105472
#define KVBUF    (TK * QP * 2)

__global__ __launch_bounds__(128, 2)
void attn_kernel(const float* __restrict__ x, const int* __restrict__ mask,
                 const float* __restrict__ gamma, const float* __restrict__ beta,
                 float* __restrict__ out)
{
    extern __shared__ char smraw[];
    char* sm = smraw;
    __half* Qh  = (__half*)(sm + SMEM_Q);
    __half* Kh  = (__half*)(sm + SMEM_K);
    __half* Vh  = (__half*)(sm + SMEM_V);
    __half* Ph  = (__half*)(sm + SMEM_P);
    __half* mk  = (__half*)(sm + SMEM_MK);
    float*  gms = (float*)(sm + SMEM_GB);
    float*  bts = gms + 128;

    const int tid = threadIdx.x, lane = tid & 31, wid = tid >> 5;
    const int b  = blockIdx.x >> 6;
    const int qb = (blockIdx.x & 63) * TQ;
    const int r0 = wid * 16;
    const int g  = lane >> 2, qd = lane & 3;

    // Q tile: 64 rows x 256B
    for (int i = tid; i < 1024; i += 128) {
        int row = i >> 4, c8 = (i & 15) * 8;
        *(uint4*)(Qh + row * QP + c8) =
            *(const uint4*)(g_Q + ((size_t)(b * NTOK + qb + row)) * CH + c8);
    }
    // mask as fp16 additive (-60000 ~ -inf after softmax)
    for (int i = tid; i < NTOK; i += 128)
        mk[i] = (mask[b * NTOK + i] > 0) ? __float2half(0.0f) : __float2half(-60000.0f);
    if (tid < 128) { gms[tid] = gamma[tid]; bts[tid] = beta[tid]; }

    {
        const __half* Ksrc = g_K + ((size_t)(b * NTOK)) * CH;
        const __half* Vsrc = g_V + ((size_t)(b * NTOK)) * CH;
        for (int i = tid; i < 1024; i += 128) {
            int row = i >> 4, c8 = (i & 15) * 8;
            cp16(smem_u32(Kh + row * QP + c8), Ksrc + row * CH + c8);
            cp16(smem_u32(Vh + row * QP + c8), Vsrc + row * CH + c8);
        }
        cp_commit();
    }

    const unsigned aQ  = smem_u32(Qh) + ((r0 + (lane & 15)) * QP + ((lane >> 4) * 8)) * 2;
    const unsigned aP  = smem_u32(Ph) + ((r0 + (lane & 15)) * PP + ((lane >> 4) * 8)) * 2;
    const unsigned aK4 = smem_u32(Kh) + (((lane >> 4) * 8 + (lane & 7)) * QP + ((lane >> 3) & 1) * 8) * 2;
    const unsigned aV4 = smem_u32(Vh) + ((lane & 15) * QP) * 2 + (lane >> 4) * 16;

    float m_A = -INFINITY, m_B = -INFINITY, l_A = 0.f, l_B = 0.f;
    float o[16][4];
    #pragma unroll
    for (int i = 0; i < 16; i++) { o[i][0] = o[i][1] = o[i][2] = o[i][3] = 0.f; }

    for (int kt = 0; kt < NTOK / TK; kt++) {
        if (kt < NTOK / TK - 1) {
            int nbuf = (kt + 1) & 1;
            const __half* Ksrc = g_K + ((size_t)(b * NTOK + (kt + 1) * TK)) * CH;
            const __half* Vsrc = g_V + ((size_t)(b * NTOK + (kt + 1) * TK)) * CH;
            for (int i = tid; i < 1024; i += 128) {
                int row = i >> 4, c8 = (i & 15) * 8;
                cp16(smem_u32(Kh + nbuf * (TK * QP) + row * QP + c8), Ksrc + row * CH + c8);
                cp16(smem_u32(Vh + nbuf * (TK * QP) + row * QP + c8), Vsrc + row * CH + c8);
            }
            cp_commit();
            cp_wait<1>();
        } else {
            cp_wait<0>();
        }
        __syncthreads();

        const unsigned kOff = (kt & 1) * KVBUF;

        // ---- scores S = Q K^T : 16 x 64 per warp ----
        float c[8][4];
        #pragma unroll
        for (int nt = 0; nt < 8; nt++) { c[nt][0] = c[nt][1] = c[nt][2] = c[nt][3] = 0.f; }

        #pragma unroll
        for (int ks = 0; ks < 8; ks++) {
            unsigned a0, a1, a2, a3;
            ldsm4(aQ + ks * 32, a0, a1, a2, a3);
            #pragma unroll
            for (int ntp = 0; ntp < 4; ntp++) {
                unsigned b0, b1, b2, b3;
                ldsm4(aK4 + kOff + ntp * (16 * QP * 2) + ks * 32, b0, b1, b2, b3);
                mma16816(c[2*ntp][0], c[2*ntp][1], c[2*ntp][2], c[2*ntp][3],
                         a0, a1, a2, a3, b0, b1);
                mma16816(c[2*ntp+1][0], c[2*ntp+1][1], c[2*ntp+1][2], c[2*ntp+1][3],
                         a0, a1, a2, a3, b2, b3);
            }
        }

        // ---- mask + warp-local online softmax ----
        const __half* mkt = mk + kt * TK;
        float rmA = -INFINITY, rmB = -INFINITY;
        #pragma unroll
        for (int nt = 0; nt < 8; nt++) {
            float2 mf = __half22float2(*(const __half2*)&mkt[nt * 8 + 2 * qd]);
            c[nt][0] += mf.x; c[nt][1] += mf.y; c[nt][2] += mf.x; c[nt][3] += mf.y;
            rmA = fmaxf(rmA, fmaxf(c[nt][0], c[nt][1]));
            rmB = fmaxf(rmB, fmaxf(c[nt][2], c[nt][3]));
        }
        rmA = fmaxf(rmA, __shfl_xor_sync(0xffffffffu, rmA, 1));
        rmA = fmaxf(rmA, __shfl_xor_sync(0xffffffffu, rmA, 2));
        rmB = fmaxf(rmB, __shfl_xor_sync(0xffffffffu, rmB, 1));
        rmB = fmaxf(rmB, __shfl_xor_sync(0xffffffffu, rmB, 2));

        float nmA = fmaxf(m_A, rmA), nmB = fmaxf(m_B, rmB);
        float sclA = __expf(m_A - nmA), sclB = __expf(m_B - nmB);
        m_A = nmA; m_B = nmB;

        float rsA = 0.f, rsB = 0.f;
        #pragma unroll
        for (int nt = 0; nt < 8; nt++) {
            float p0 = __expf(c[nt][0] - nmA), p1 = __expf(c[nt][1] - nmA);
            float p2 = __expf(c[nt][2] - nmB), p3 = __expf(c[nt][3] - nmB);
            rsA += p0 + p1; rsB += p2 + p3;
            *(__half2*)(Ph + (r0 + g) * PP + nt * 8 + 2 * qd)     = __floats2half2_rn(p0, p1);
            *(__half2*)(Ph + (r0 + g + 8) * PP + nt * 8 + 2 * qd) = __floats2half2_rn(p2, p3);
        }
        rsA += __shfl_xor_sync(0xffffffffu, rsA, 1);
        rsA += __shfl_xor_sync(0xffffffffu, rsA, 2);
        rsB += __shfl_xor_sync(0xffffffffu, rsB, 1);
        rsB += __shfl_xor_sync(0xffffffffu, rsB, 2);
        l_A = l_A * sclA + rsA;
        l_B = l_B * sclB + rsB;

        #pragma unroll
        for (int nt2 = 0; nt2 < 16; nt2++) {
            o[nt2][0] *= sclA; o[nt2][1] *= sclA;
            o[nt2][2] *= sclB; o[nt2][3] *= sclB;
        }
        __syncwarp();

        // ---- O += P @ V : 16 x 128 per warp ----
        #pragma unroll
        for (int ks = 0; ks < 4; ks++) {
            unsigned a0, a1, a2, a3;
            ldsm4(aP + ks * 32, a0, a1, a2, a3);
            #pragma unroll
            for (int ntp = 0; ntp < 8; ntp++) {
                unsigned b0, b1, b2, b3;
                ldsm4t(aV4 + kOff + ks * (16 * QP * 2) + ntp * 32, b0, b1, b2, b3);
                mma16816(o[2*ntp][0], o[2*ntp][1], o[2*ntp][2], o[2*ntp][3],
                         a0, a1, a2, a3, b0, b1);
                mma16816(o[2*ntp+1][0], o[2*ntp+1][1], o[2*ntp+1][2], o[2*ntp+1][3],
                         a0, a1, a2, a3, b2, b3);
            }
        }
        __syncthreads();
    }

    // ---- epilogue: normalize, residual, LayerNorm, store ----
    const float invA = 1.f / l_A, invB = 1.f / l_B;
    const int nA = qb + r0 + g, nB = nA + 8;

    #pragma unroll
    for (int half = 0; half < 2; half++) {
        const int n = half ? nB : nA;
        const float inv = half ? invB : invA;
        float vals[32];
        float sum = 0.f, sq = 0.f;
        #pragma unroll
        for (int nt2 = 0; nt2 < 16; nt2++) {
            #pragma unroll
            for (int j = 0; j < 2; j++) {
                int co = nt2 * 8 + 2 * qd + j;
                float val = o[nt2][2 * half + j] * inv
                          + x[((size_t)(b * CH + co)) * NTOK + n];
                vals[nt2 * 2 + j] = val;
                sum += val; sq += val * val;
            }
        }
        sum += __shfl_xor_sync(0xffffffffu, sum, 1);
        sum += __shfl_xor_sync(0xffffffffu, sum, 2);
        sq  += __shfl_xor_sync(0xffffffffu, sq, 1);
        sq  += __shfl_xor_sync(0xffffffffu, sq, 2);
        float mu   = sum * (1.f / 128.f);
        float var  = sq * (1.f / 128.f) - mu * mu;
        float rstd = rsqrtf(var + 1e-5f);
        #pragma unroll
        for (int nt2 = 0; nt2 < 16; nt2++) {
            #pragma unroll
            for (int j = 0; j < 2; j++) {
                int co = nt2 * 8 + 2 * qd + j;
                out[((size_t)(b * CH + co)) * NTOK + n] =
                    (vals[nt2 * 2 + j] - mu) * rstd * gms[co] + bts[co];
            }
        }
    }
}

// ---------------------------------------------------------------------------
extern "C" void kernel_launch(void* const* d_in, const int* in_sizes, int n_in,
                              void* d_out, int out_size)
{
    const float* prompt = (const float*)d_in[0];
    const float* x      = (const float*)d_in[1];
    const float* Wq     = (const float*)d_in[2];
    const float* bq     = (const float*)d_in[3];
    const float* Wk     = (const float*)d_in[4];
    const float* bk     = (const float*)d_in[5];
    const float* Wv     = (const float*)d_in[6];
    const float* bv     = (const float*)d_in[7];
    const float* gamma  = (const float*)d_in[8];
    const float* beta   = (const float*)d_in[9];
    const int*   mask   = (const int*)d_in[10];
    float* out = (float*)d_out;

    const int qkv_smem = (5 * 128 * WPI) * 2 + 3 * 128 * (int)sizeof(float); // 175616

    cudaFuncSetAttribute(qkv_kernel,  cudaFuncAttributeMaxDynamicSharedMemorySize, qkv_smem);
    cudaFuncSetAttribute(attn_kernel, cudaFuncAttributeMaxDynamicSharedMemorySize, SMEM_TOT);

    qkv_kernel<<<BATCH * 32, 256, qkv_smem>>>(prompt, x, Wq, bq, Wk, bk, Wv, bv);
    attn_kernel<<<BATCH * (NTOK / TQ), 128, SMEM_TOT>>>(x, mask, gamma, beta, out);
}

// round 9
// speedup vs baseline: 1.0045x; 1.0045x over previous
#include <cuda_runtime.h>
#include <cuda_fp16.h>
#include <math.h>

#define BATCH 4
#define CH    128
#define NTOK  4096
#define TQ    64
#define TK    64
#define QP    136   // Q/K/V smem pitch (halves); 272B stride -> conflict-free ldmatrix
#define PP    72    // P smem pitch (halves)
#define WPI   136   // qkv smem pitch

// fp16 staging buffers written by qkv kernel (Q pre-scaled by 1/sqrt(C)).
__device__ __half g_Q[BATCH * NTOK * CH];
__device__ __half g_K[BATCH * NTOK * CH];
__device__ __half g_V[BATCH * NTOK * CH];

// ---------------------------------------------------------------------------
// PTX helpers
// ---------------------------------------------------------------------------
__device__ __forceinline__ unsigned smem_u32(const void* p) {
    return (unsigned)__cvta_generic_to_shared(p);
}
__device__ __forceinline__ void cp16(unsigned dst, const void* src) {
    asm volatile("cp.async.cg.shared.global [%0], [%1], 16;\n" :: "r"(dst), "l"(src));
}
__device__ __forceinline__ void cp_commit() {
    asm volatile("cp.async.commit_group;\n");
}
template<int N> __device__ __forceinline__ void cp_wait() {
    asm volatile("cp.async.wait_group %0;\n" :: "n"(N));
}
__device__ __forceinline__ void ldsm4(unsigned addr, unsigned& a0, unsigned& a1,
                                      unsigned& a2, unsigned& a3) {
    asm volatile("ldmatrix.sync.aligned.m8n8.x4.shared.b16 {%0,%1,%2,%3}, [%4];\n"
                 : "=r"(a0), "=r"(a1), "=r"(a2), "=r"(a3) : "r"(addr));
}
__device__ __forceinline__ void ldsm4t(unsigned addr, unsigned& a0, unsigned& a1,
                                       unsigned& a2, unsigned& a3) {
    asm volatile("ldmatrix.sync.aligned.m8n8.x4.trans.shared.b16 {%0,%1,%2,%3}, [%4];\n"
                 : "=r"(a0), "=r"(a1), "=r"(a2), "=r"(a3) : "r"(addr));
}
__device__ __forceinline__ void mma16816(float& d0, float& d1, float& d2, float& d3,
                                         unsigned a0, unsigned a1, unsigned a2, unsigned a3,
                                         unsigned b0, unsigned b1) {
    asm volatile("mma.sync.aligned.m16n8k16.row.col.f32.f16.f16.f32 "
                 "{%0,%1,%2,%3}, {%4,%5,%6,%7}, {%8,%9}, {%0,%1,%2,%3};\n"
                 : "+f"(d0), "+f"(d1), "+f"(d2), "+f"(d3)
                 : "r"(a0), "r"(a1), "r"(a2), "r"(a3), "r"(b0), "r"(b1));
}

// ---------------------------------------------------------------------------
// Kernel 1: tensor-core QKV. Block = 128 tokens; computes Q,K,V projections.
// Warp = 16 tokens x 128 outputs. fp32 gmem -> fp16 smem -> mma (fp32 accum).
// ---------------------------------------------------------------------------
__global__ __launch_bounds__(256, 1)
void qkv_kernel(const float* __restrict__ prompt, const float* __restrict__ x,
                const float* __restrict__ Wq, const float* __restrict__ bq,
                const float* __restrict__ Wk, const float* __restrict__ bk,
                const float* __restrict__ Wv, const float* __restrict__ bv)
{
    extern __shared__ char smraw[];
    __half* Xp  = (__half*)smraw;           // prompt tile 128x136
    __half* Xx  = Xp  + 128 * WPI;          // x tile
    __half* Wqs = Xx  + 128 * WPI;          // 128x136 each
    __half* Wks = Wqs + 128 * WPI;
    __half* Wvs = Wks + 128 * WPI;
    float*  bqs = (float*)(Wvs + 128 * WPI);
    float*  bks = bqs + 128;
    float*  bvs = bks + 128;

    const int b  = blockIdx.x >> 5;
    const int nb = (blockIdx.x & 31) * 128;
    const int tid = threadIdx.x;

    for (int idx = tid; idx < 128 * 128; idx += 256) {
        int c = idx >> 7, t = idx & 127;
        size_t gofs = ((size_t)b * CH + c) * NTOK + nb + t;
        Xp[t * WPI + c] = __float2half(prompt[gofs]);
        Xx[t * WPI + c] = __float2half(x[gofs]);
    }
    for (int idx = tid; idx < 128 * 128; idx += 256) {
        int co = idx >> 7, c = idx & 127;
        Wqs[co * WPI + c] = __float2half(Wq[idx]);
        Wks[co * WPI + c] = __float2half(Wk[idx]);
        Wvs[co * WPI + c] = __float2half(Wv[idx]);
    }
    if (tid < 128) { bqs[tid] = bq[tid]; bks[tid] = bk[tid]; bvs[tid] = bv[tid]; }
    __syncthreads();

    const int lane = tid & 31, wid = tid >> 5;
    const int r0 = wid * 16;
    const int g = lane >> 2, qd = lane & 3;

    const unsigned aXp = smem_u32(Xp) + ((r0 + (lane & 15)) * WPI + (lane >> 4) * 8) * 2;
    const unsigned aXx = aXp + (unsigned)(128 * WPI * 2);
    const unsigned w4 = (((lane >> 4) * 8 + (lane & 7)) * WPI + ((lane >> 3) & 1) * 8) * 2;

    #pragma unroll 1
    for (int p = 0; p < 3; p++) {
        const unsigned aA = (p == 0) ? aXp : aXx;
        const unsigned aW = smem_u32(p == 0 ? Wqs : (p == 1 ? Wks : Wvs)) + w4;
        const float* bias = (p == 0) ? bqs : (p == 1) ? bks : bvs;
        __half* outg      = (p == 0) ? g_Q : (p == 1) ? g_K : g_V;
        const float os    = (p == 0) ? 0.0883883476483184f : 1.0f;

        float c[16][4];
        #pragma unroll
        for (int nt = 0; nt < 16; nt++) { c[nt][0] = c[nt][1] = c[nt][2] = c[nt][3] = 0.f; }

        #pragma unroll
        for (int ks = 0; ks < 8; ks++) {
            unsigned a0, a1, a2, a3;
            ldsm4(aA + ks * 32, a0, a1, a2, a3);
            #pragma unroll
            for (int ntp = 0; ntp < 8; ntp++) {
                unsigned b0, b1, b2, b3;
                ldsm4(aW + ntp * (16 * WPI * 2) + ks * 32, b0, b1, b2, b3);
                mma16816(c[2*ntp][0], c[2*ntp][1], c[2*ntp][2], c[2*ntp][3],
                         a0, a1, a2, a3, b0, b1);
                mma16816(c[2*ntp+1][0], c[2*ntp+1][1], c[2*ntp+1][2], c[2*ntp+1][3],
                         a0, a1, a2, a3, b2, b3);
            }
        }

        __half* row0 = outg + (size_t)(b * NTOK + nb + r0 + g) * CH;
        __half* row1 = row0 + 8 * CH;
        #pragma unroll
        for (int nt = 0; nt < 16; nt++) {
            int co = nt * 8 + 2 * qd;
            float b0v = bias[co], b1v = bias[co + 1];
            *(__half2*)(row0 + co) = __floats2half2_rn((c[nt][0] + b0v) * os, (c[nt][1] + b1v) * os);
            *(__half2*)(row1 + co) = __floats2half2_rn((c[nt][2] + b0v) * os, (c[nt][3] + b1v) * os);
        }
    }
}

// ---------------------------------------------------------------------------
// Kernel 2: fp16 tensor-core flash attention + residual + LayerNorm.
// Block = 64 queries, 4 warps, ~103KB smem -> 2 blocks/SM for latency overlap.
// Warp = 16 rows x 64 keys; warp-local softmax; x4 ldmatrix for K/V.
// ---------------------------------------------------------------------------
#define SMEM_Q   0                // 64*136*2 = 17408
#define SMEM_K   17408            // 2 bufs x 64*136*2 = 34816
#define SMEM_V   52224            // 34816
#define SMEM_P   87040            // 64*72*2 = 9216
#define SMEM_MK  96256            // 4096 halves = 8192
#define SMEM_GB  104448           // 256 floats = 1024
#define SMEM_TOT 105472
#define KVBUF    (TK * QP * 2)

__global__ __launch_bounds__(128, 2)
void attn_kernel(const float* __restrict__ x, const int* __restrict__ mask,
                 const float* __restrict__ gamma, const float* __restrict__ beta,
                 float* __restrict__ out)
{
    extern __shared__ char smraw[];
    char* sm = smraw;
    __half* Qh  = (__half*)(sm + SMEM_Q);
    __half* Kh  = (__half*)(sm + SMEM_K);
    __half* Vh  = (__half*)(sm + SMEM_V);
    __half* Ph  = (__half*)(sm + SMEM_P);
    __half* mk  = (__half*)(sm + SMEM_MK);
    float*  gms = (float*)(sm + SMEM_GB);
    float*  bts = gms + 128;

    const int tid = threadIdx.x, lane = tid & 31, wid = tid >> 5;
    const int b  = blockIdx.x >> 6;
    const int qb = (blockIdx.x & 63) * TQ;
    const int r0 = wid * 16;
    const int g  = lane >> 2, qd = lane & 3;

    // Q tile: 64 rows x 256B
    for (int i = tid; i < 1024; i += 128) {
        int row = i >> 4, c8 = (i & 15) * 8;
        *(uint4*)(Qh + row * QP + c8) =
            *(const uint4*)(g_Q + ((size_t)(b * NTOK + qb + row)) * CH + c8);
    }
    // mask as fp16 additive (-60000 ~ -inf after softmax)
    for (int i = tid; i < NTOK; i += 128)
        mk[i] = (mask[b * NTOK + i] > 0) ? __float2half(0.0f) : __float2half(-60000.0f);
    if (tid < 128) { gms[tid] = gamma[tid]; bts[tid] = beta[tid]; }

    {
        const __half* Ksrc = g_K + ((size_t)(b * NTOK)) * CH;
        const __half* Vsrc = g_V + ((size_t)(b * NTOK)) * CH;
        for (int i = tid; i < 1024; i += 128) {
            int row = i >> 4, c8 = (i & 15) * 8;
            cp16(smem_u32(Kh + row * QP + c8), Ksrc + row * CH + c8);
            cp16(smem_u32(Vh + row * QP + c8), Vsrc + row * CH + c8);
        }
        cp_commit();
    }

    const unsigned aQ  = smem_u32(Qh) + ((r0 + (lane & 15)) * QP + ((lane >> 4) * 8)) * 2;
    const unsigned aP  = smem_u32(Ph) + ((r0 + (lane & 15)) * PP + ((lane >> 4) * 8)) * 2;
    const unsigned aK4 = smem_u32(Kh) + (((lane >> 4) * 8 + (lane & 7)) * QP + ((lane >> 3) & 1) * 8) * 2;
    const unsigned aV4 = smem_u32(Vh) + ((lane & 15) * QP) * 2 + (lane >> 4) * 16;

    float m_A = -INFINITY, m_B = -INFINITY, l_A = 0.f, l_B = 0.f;
    float o[16][4];
    #pragma unroll
    for (int i = 0; i < 16; i++) { o[i][0] = o[i][1] = o[i][2] = o[i][3] = 0.f; }

    for (int kt = 0; kt < NTOK / TK; kt++) {
        if (kt < NTOK / TK - 1) {
            int nbuf = (kt + 1) & 1;
            const __half* Ksrc = g_K + ((size_t)(b * NTOK + (kt + 1) * TK)) * CH;
            const __half* Vsrc = g_V + ((size_t)(b * NTOK + (kt + 1) * TK)) * CH;
            for (int i = tid; i < 1024; i += 128) {
                int row = i >> 4, c8 = (i & 15) * 8;
                cp16(smem_u32(Kh + nbuf * (TK * QP) + row * QP + c8), Ksrc + row * CH + c8);
                cp16(smem_u32(Vh + nbuf * (TK * QP) + row * QP + c8), Vsrc + row * CH + c8);
            }
            cp_commit();
            cp_wait<1>();
        } else {
            cp_wait<0>();
        }
        __syncthreads();

        const unsigned kOff = (kt & 1) * KVBUF;

        // ---- scores S = Q K^T : 16 x 64 per warp ----
        float c[8][4];
        #pragma unroll
        for (int nt = 0; nt < 8; nt++) { c[nt][0] = c[nt][1] = c[nt][2] = c[nt][3] = 0.f; }

        #pragma unroll
        for (int ks = 0; ks < 8; ks++) {
            unsigned a0, a1, a2, a3;
            ldsm4(aQ + ks * 32, a0, a1, a2, a3);
            #pragma unroll
            for (int ntp = 0; ntp < 4; ntp++) {
                unsigned b0, b1, b2, b3;
                ldsm4(aK4 + kOff + ntp * (16 * QP * 2) + ks * 32, b0, b1, b2, b3);
                mma16816(c[2*ntp][0], c[2*ntp][1], c[2*ntp][2], c[2*ntp][3],
                         a0, a1, a2, a3, b0, b1);
                mma16816(c[2*ntp+1][0], c[2*ntp+1][1], c[2*ntp+1][2], c[2*ntp+1][3],
                         a0, a1, a2, a3, b2, b3);
            }
        }

        // ---- mask + warp-local online softmax ----
        const __half* mkt = mk + kt * TK;
        float rmA = -INFINITY, rmB = -INFINITY;
        #pragma unroll
        for (int nt = 0; nt < 8; nt++) {
            float2 mf = __half22float2(*(const __half2*)&mkt[nt * 8 + 2 * qd]);
            c[nt][0] += mf.x; c[nt][1] += mf.y; c[nt][2] += mf.x; c[nt][3] += mf.y;
            rmA = fmaxf(rmA, fmaxf(c[nt][0], c[nt][1]));
            rmB = fmaxf(rmB, fmaxf(c[nt][2], c[nt][3]));
        }
        rmA = fmaxf(rmA, __shfl_xor_sync(0xffffffffu, rmA, 1));
        rmA = fmaxf(rmA, __shfl_xor_sync(0xffffffffu, rmA, 2));
        rmB = fmaxf(rmB, __shfl_xor_sync(0xffffffffu, rmB, 1));
        rmB = fmaxf(rmB, __shfl_xor_sync(0xffffffffu, rmB, 2));

        float nmA = fmaxf(m_A, rmA), nmB = fmaxf(m_B, rmB);
        float sclA = __expf(m_A - nmA), sclB = __expf(m_B - nmB);
        m_A = nmA; m_B = nmB;

        float rsA = 0.f, rsB = 0.f;
        #pragma unroll
        for (int nt = 0; nt < 8; nt++) {
            float p0 = __expf(c[nt][0] - nmA), p1 = __expf(c[nt][1] - nmA);
            float p2 = __expf(c[nt][2] - nmB), p3 = __expf(c[nt][3] - nmB);
            rsA += p0 + p1; rsB += p2 + p3;
            *(__half2*)(Ph + (r0 + g) * PP + nt * 8 + 2 * qd)     = __floats2half2_rn(p0, p1);
            *(__half2*)(Ph + (r0 + g + 8) * PP + nt * 8 + 2 * qd) = __floats2half2_rn(p2, p3);
        }
        rsA += __shfl_xor_sync(0xffffffffu, rsA, 1);
        rsA += __shfl_xor_sync(0xffffffffu, rsA, 2);
        rsB += __shfl_xor_sync(0xffffffffu, rsB, 1);
        rsB += __shfl_xor_sync(0xffffffffu, rsB, 2);
        l_A = l_A * sclA + rsA;
        l_B = l_B * sclB + rsB;

        #pragma unroll
        for (int nt2 = 0; nt2 < 16; nt2++) {
            o[nt2][0] *= sclA; o[nt2][1] *= sclA;
            o[nt2][2] *= sclB; o[nt2][3] *= sclB;
        }
        __syncwarp();

        // ---- O += P @ V : 16 x 128 per warp ----
        #pragma unroll
        for (int ks = 0; ks < 4; ks++) {
            unsigned a0, a1, a2, a3;
            ldsm4(aP + ks * 32, a0, a1, a2, a3);
            #pragma unroll
            for (int ntp = 0; ntp < 8; ntp++) {
                unsigned b0, b1, b2, b3;
                ldsm4t(aV4 + kOff + ks * (16 * QP * 2) + ntp * 32, b0, b1, b2, b3);
                mma16816(o[2*ntp][0], o[2*ntp][1], o[2*ntp][2], o[2*ntp][3],
                         a0, a1, a2, a3, b0, b1);
                mma16816(o[2*ntp+1][0], o[2*ntp+1][1], o[2*ntp+1][2], o[2*ntp+1][3],
                         a0, a1, a2, a3, b2, b3);
            }
        }
        __syncthreads();
    }

    // ---- epilogue: normalize, residual, LayerNorm, store ----
    const float invA = 1.f / l_A, invB = 1.f / l_B;
    const int nA = qb + r0 + g, nB = nA + 8;

    #pragma unroll
    for (int half = 0; half < 2; half++) {
        const int n = half ? nB : nA;
        const float inv = half ? invB : invA;
        float vals[32];
        float sum = 0.f, sq = 0.f;
        #pragma unroll
        for (int nt2 = 0; nt2 < 16; nt2++) {
            #pragma unroll
            for (int j = 0; j < 2; j++) {
                int co = nt2 * 8 + 2 * qd + j;
                float val = o[nt2][2 * half + j] * inv
                          + x[((size_t)(b * CH + co)) * NTOK + n];
                vals[nt2 * 2 + j] = val;
                sum += val; sq += val * val;
            }
        }
        sum += __shfl_xor_sync(0xffffffffu, sum, 1);
        sum += __shfl_xor_sync(0xffffffffu, sum, 2);
        sq  += __shfl_xor_sync(0xffffffffu, sq, 1);
        sq  += __shfl_xor_sync(0xffffffffu, sq, 2);
        float mu   = sum * (1.f / 128.f);
        float var  = sq * (1.f / 128.f) - mu * mu;
        float rstd = rsqrtf(var + 1e-5f);
        #pragma unroll
        for (int nt2 = 0; nt2 < 16; nt2++) {
            #pragma unroll
            for (int j = 0; j < 2; j++) {
                int co = nt2 * 8 + 2 * qd + j;
                out[((size_t)(b * CH + co)) * NTOK + n] =
                    (vals[nt2 * 2 + j] - mu) * rstd * gms[co] + bts[co];
            }
        }
    }
}

// ---------------------------------------------------------------------------
extern "C" void kernel_launch(void* const* d_in, const int* in_sizes, int n_in,
                              void* d_out, int out_size)
{
    const float* prompt = (const float*)d_in[0];
    const float* x      = (const float*)d_in[1];
    const float* Wq     = (const float*)d_in[2];
    const float* bq     = (const float*)d_in[3];
    const float* Wk     = (const float*)d_in[4];
    const float* bk     = (const float*)d_in[5];
    const float* Wv     = (const float*)d_in[6];
    const float* bv     = (const float*)d_in[7];
    const float* gamma  = (const float*)d_in[8];
    const float* beta   = (const float*)d_in[9];
    const int*   mask   = (const int*)d_in[10];
    float* out = (float*)d_out;

    const int qkv_smem = (5 * 128 * WPI) * 2 + 3 * 128 * (int)sizeof(float); // 175616

    cudaFuncSetAttribute(qkv_kernel,  cudaFuncAttributeMaxDynamicSharedMemorySize, qkv_smem);
    cudaFuncSetAttribute(attn_kernel, cudaFuncAttributeMaxDynamicSharedMemorySize, SMEM_TOT);

    qkv_kernel<<<BATCH * 32, 256, qkv_smem>>>(prompt, x, Wq, bq, Wk, bk, Wv, bv);
    attn_kernel<<<BATCH * (NTOK / TQ), 128, SMEM_TOT>>>(x, mask, gamma, beta, out);
}